// round 1
// baseline (speedup 1.0000x reference)
#include <cuda_runtime.h>
#include <math.h>

#define HID 1024
#define NH 16
#define HD 64
#define BLK 64
#define MAXM 16384
#define NEGV -1000000000.0f

// Scratch (device globals: no allocations allowed)
__device__ float g_q[MAXM * HID];
__device__ float g_k[MAXM * HID];
__device__ float g_v[MAXM * HID];
__device__ float g_ctx[MAXM * HID];
__device__ float g_y[MAXM * HID];

// ---------------------------------------------------------------------------
// GEMM: out[m,n] = sum_k X[m,k] * W[n,k] + bias[n]  (Y = X @ W^T + b)
// MODE 0: write transposed to [ (b*NH+h)*S + t ]*64 + d   (QKV path)
// MODE 1: write row-major + residual                       (O-proj path)
// Tile 128x128x8, 256 threads, 8x8 microtile.
// ---------------------------------------------------------------------------
template <int MODE>
__global__ void __launch_bounds__(256, 2)
gemm_kernel(const float* __restrict__ X, const float* __restrict__ W,
            const float* __restrict__ bias, const float* __restrict__ resid,
            float* __restrict__ out, int M, int S)
{
    const int K = HID;
    __shared__ float As[8 * 132];
    __shared__ float Bs[8 * 132];

    const int tid = threadIdx.x;
    const int tx = tid & 15;
    const int ty = tid >> 4;
    const int mBase = blockIdx.y * 128;
    const int nBase = blockIdx.x * 128;

    const int lr = tid >> 1;          // 0..127 tile row
    const int lk = (tid & 1) << 2;    // 0 or 4

    const float* aPtr = X + (size_t)(mBase + lr) * K + lk;
    const float* bPtr = W + (size_t)(nBase + lr) * K + lk;

    float4 aReg = *(const float4*)aPtr;
    float4 bReg = *(const float4*)bPtr;

    float acc[8][8];
#pragma unroll
    for (int i = 0; i < 8; ++i)
#pragma unroll
        for (int j = 0; j < 8; ++j) acc[i][j] = 0.f;

    for (int k0 = 0; k0 < K; k0 += 8) {
        As[(lk + 0) * 132 + lr] = aReg.x;
        As[(lk + 1) * 132 + lr] = aReg.y;
        As[(lk + 2) * 132 + lr] = aReg.z;
        As[(lk + 3) * 132 + lr] = aReg.w;
        Bs[(lk + 0) * 132 + lr] = bReg.x;
        Bs[(lk + 1) * 132 + lr] = bReg.y;
        Bs[(lk + 2) * 132 + lr] = bReg.z;
        Bs[(lk + 3) * 132 + lr] = bReg.w;
        __syncthreads();

        if (k0 + 8 < K) {   // prefetch next k-slab while computing
            aReg = *(const float4*)(aPtr + k0 + 8);
            bReg = *(const float4*)(bPtr + k0 + 8);
        }

#pragma unroll
        for (int kk = 0; kk < 8; ++kk) {
            float4 a0 = *(const float4*)(As + kk * 132 + (ty << 2));
            float4 a1 = *(const float4*)(As + kk * 132 + 64 + (ty << 2));
            float4 b0 = *(const float4*)(Bs + kk * 132 + (tx << 2));
            float4 b1 = *(const float4*)(Bs + kk * 132 + 64 + (tx << 2));
            float av[8] = {a0.x, a0.y, a0.z, a0.w, a1.x, a1.y, a1.z, a1.w};
            float bw[8] = {b0.x, b0.y, b0.z, b0.w, b1.x, b1.y, b1.z, b1.w};
#pragma unroll
            for (int i = 0; i < 8; ++i)
#pragma unroll
                for (int j = 0; j < 8; ++j)
                    acc[i][j] = fmaf(av[i], bw[j], acc[i][j]);
        }
        __syncthreads();
    }

#pragma unroll
    for (int i = 0; i < 8; ++i) {
        int m = mBase + (ty << 2) + (i & 3) + ((i >> 2) << 6);
#pragma unroll
        for (int j = 0; j < 8; ++j) {
            int n = nBase + (tx << 2) + (j & 3) + ((j >> 2) << 6);
            float val = acc[i][j] + bias[n];
            if (MODE == 0) {
                int bb = m / S;
                int t = m - bb * S;
                int h = n >> 6;
                int d = n & 63;
                out[((size_t)(bb * NH + h) * S + t) * HD + d] = val;
            } else {
                size_t off = (size_t)m * HID + n;
                out[off] = val + resid[off];
            }
        }
    }
}

// ---------------------------------------------------------------------------
// Block-sparse attention. One CTA per (b, h, qblock). 256 threads.
// Thread (r = tid/4, cs = tid%4): owns query row r, columns c = cs + 4*i.
// smem: qs[64*65], kv[64*65] (k then v tiles), sc[64*260] (scores->probs)
// ---------------------------------------------------------------------------
__global__ void __launch_bounds__(256)
attn_kernel(const float* __restrict__ gq, const float* __restrict__ gk,
            const float* __restrict__ gv, const float* __restrict__ mask,
            float* __restrict__ gctx, int S, int nblk)
{
    extern __shared__ float sm[];
    float* qs = sm;                  // 64*65
    float* kv = sm + 64 * 65;        // 64*65
    float* sc = sm + 2 * 64 * 65;    // 64*260

    const int tid = threadIdx.x;
    const int qb = blockIdx.x % nblk;
    const int bh = blockIdx.x / nblk;
    const int b = bh >> 4;           // NH = 16
    const int h = bh & 15;

    // BigBird layout: cands = [0, qb-1, qb, qb+1], dedup'd, range-checked
    int cnd[4] = {0, qb - 1, qb, qb + 1};
    int kbi[4];
    int vld[4];
#pragma unroll
    for (int c = 0; c < 4; ++c) {
        int cc = cnd[c];
        int ok = (cc >= 0 && cc < nblk);
#pragma unroll
        for (int j = 0; j < 4; ++j)
            if (j < c && vld[j] && cnd[j] == cc) ok = 0;
        vld[c] = ok;
        kbi[c] = min(max(cc, 0), nblk - 1);
    }

    // load q tile (64x64) -> qs (stride 65)
    {
        const float* qptr = gq + ((size_t)bh * S + (size_t)qb * BLK) * HD;
        for (int i = tid; i < BLK * HD; i += 256)
            qs[(i >> 6) * 65 + (i & 63)] = qptr[i];
    }

    const int r = tid >> 2;
    const int cs = tid & 3;
    const float scale = 0.125f;  // 1/sqrt(64)

    // ---- scores: 4 key blocks ----
    for (int m = 0; m < 4; ++m) {
        __syncthreads();  // kv reuse fence (also covers qs on m==0)
        {
            const float* kptr = gk + ((size_t)bh * S + (size_t)kbi[m] * BLK) * HD;
            for (int i = tid; i < BLK * HD; i += 256)
                kv[(i >> 6) * 65 + (i & 63)] = kptr[i];
        }
        __syncthreads();

        float s[16];
#pragma unroll
        for (int i = 0; i < 16; ++i) s[i] = 0.f;

#pragma unroll 4
        for (int d = 0; d < HD; ++d) {
            float qv = qs[r * 65 + d];
#pragma unroll
            for (int i = 0; i < 16; ++i)
                s[i] = fmaf(qv, kv[(cs + 4 * i) * 65 + d], s[i]);
        }

        float* scRow = sc + r * 260 + m * 64;
        if (vld[m]) {
            const float* mrow = mask + (size_t)b * S + (size_t)kbi[m] * BLK;
#pragma unroll
            for (int i = 0; i < 16; ++i) {
                int c = cs + 4 * i;
                scRow[c] = s[i] * scale + mrow[c];
            }
        } else {
#pragma unroll
            for (int i = 0; i < 16; ++i) scRow[cs + 4 * i] = NEGV;
        }
    }
    __syncthreads();

    // ---- softmax over 256 entries per row (4 lanes cooperate) ----
    float mx = -3.0e38f;
#pragma unroll
    for (int m = 0; m < 4; ++m)
#pragma unroll
        for (int i = 0; i < 16; ++i)
            mx = fmaxf(mx, sc[r * 260 + m * 64 + cs + 4 * i]);
    mx = fmaxf(mx, __shfl_xor_sync(0xffffffffu, mx, 1));
    mx = fmaxf(mx, __shfl_xor_sync(0xffffffffu, mx, 2));

    float sum = 0.f;
#pragma unroll
    for (int m = 0; m < 4; ++m)
#pragma unroll
        for (int i = 0; i < 16; ++i) {
            int o = r * 260 + m * 64 + cs + 4 * i;
            float e = expf(sc[o] - mx);
            sc[o] = e;
            sum += e;
        }
    sum += __shfl_xor_sync(0xffffffffu, sum, 1);
    sum += __shfl_xor_sync(0xffffffffu, sum, 2);
    const float inv = 1.f / sum;

    // ---- ctx = probs @ V (thread owns dims d = cs + 4*j) ----
    float ctx[16];
#pragma unroll
    for (int j = 0; j < 16; ++j) ctx[j] = 0.f;

    for (int m = 0; m < 4; ++m) {
        __syncthreads();  // fences sc writes (m==0) and kv reuse
        {
            const float* vptr = gv + ((size_t)bh * S + (size_t)kbi[m] * BLK) * HD;
            for (int i = tid; i < BLK * HD; i += 256)
                kv[(i >> 6) * 65 + (i & 63)] = vptr[i];
        }
        __syncthreads();

#pragma unroll 4
        for (int c = 0; c < BLK; ++c) {
            float p = sc[r * 260 + m * 64 + c];
#pragma unroll
            for (int j = 0; j < 16; ++j)
                ctx[j] = fmaf(p, kv[c * 65 + cs + 4 * j], ctx[j]);
        }
    }

    // write ctx in row-major [m, n] layout for O-projection GEMM
    {
        int t = qb * BLK + r;
        float* optr = gctx + ((size_t)(b * S + t)) * HID + h * HD;
#pragma unroll
        for (int j = 0; j < 16; ++j)
            optr[cs + 4 * j] = ctx[j] * inv;
    }
}

// ---------------------------------------------------------------------------
// LayerNorm: one CTA (256 threads) per row of 1024.
// ---------------------------------------------------------------------------
__device__ __forceinline__ float blockReduceSum(float v)
{
    __shared__ float red[8];
    __syncthreads();  // protect red[] reuse across calls
    const int lane = threadIdx.x & 31;
    const int wid = threadIdx.x >> 5;
#pragma unroll
    for (int o = 16; o; o >>= 1) v += __shfl_xor_sync(0xffffffffu, v, o);
    if (lane == 0) red[wid] = v;
    __syncthreads();
    float t = (lane < 8) ? red[lane] : 0.f;
    if (wid == 0) {
#pragma unroll
        for (int o = 4; o; o >>= 1) t += __shfl_xor_sync(0xffffffffu, t, o);
        if (lane == 0) red[0] = t;
    }
    __syncthreads();
    return red[0];
}

__global__ void __launch_bounds__(256)
ln_kernel(const float* __restrict__ y, const float* __restrict__ g,
          const float* __restrict__ bt, float* __restrict__ out)
{
    const int row = blockIdx.x;
    const int t = threadIdx.x;
    float4 v = ((const float4*)(y + (size_t)row * HID))[t];

    float s = v.x + v.y + v.z + v.w;
    float mu = blockReduceSum(s) * (1.0f / HID);

    float dx = v.x - mu, dy = v.y - mu, dz = v.z - mu, dw = v.w - mu;
    float sq = dx * dx + dy * dy + dz * dz + dw * dw;
    float var = blockReduceSum(sq) * (1.0f / HID);
    float invs = rsqrtf(var + 1e-12f);

    float4 gg = ((const float4*)g)[t];
    float4 bb = ((const float4*)bt)[t];
    float4 o;
    o.x = dx * invs * gg.x + bb.x;
    o.y = dy * invs * gg.y + bb.y;
    o.z = dz * invs * gg.z + bb.z;
    o.w = dw * invs * gg.w + bb.w;
    ((float4*)(out + (size_t)row * HID))[t] = o;
}

// ---------------------------------------------------------------------------
extern "C" void kernel_launch(void* const* d_in, const int* in_sizes, int n_in,
                              void* d_out, int out_size)
{
    const float* hidden = (const float*)d_in[0];
    const float* mask   = (const float*)d_in[1];
    const float* wq = (const float*)d_in[2];
    const float* bq = (const float*)d_in[3];
    const float* wk = (const float*)d_in[4];
    const float* bk = (const float*)d_in[5];
    const float* wv = (const float*)d_in[6];
    const float* bv = (const float*)d_in[7];
    const float* wo = (const float*)d_in[8];
    const float* bo = (const float*)d_in[9];
    const float* lng = (const float*)d_in[10];
    const float* lnb = (const float*)d_in[11];

    const int M = in_sizes[1];   // b * s
    const int S = 4096;
    const int B = M / S;
    const int nblk = S / BLK;

    float *pq, *pk, *pv, *pctx, *py;
    cudaGetSymbolAddress((void**)&pq, g_q);
    cudaGetSymbolAddress((void**)&pk, g_k);
    cudaGetSymbolAddress((void**)&pv, g_v);
    cudaGetSymbolAddress((void**)&pctx, g_ctx);
    cudaGetSymbolAddress((void**)&py, g_y);

    dim3 grid(HID / 128, M / 128);
    gemm_kernel<0><<<grid, 256>>>(hidden, wq, bq, nullptr, pq, M, S);
    gemm_kernel<0><<<grid, 256>>>(hidden, wk, bk, nullptr, pk, M, S);
    gemm_kernel<0><<<grid, 256>>>(hidden, wv, bv, nullptr, pv, M, S);

    const size_t smem = (size_t)(2 * 64 * 65 + 64 * 260) * sizeof(float);
    cudaFuncSetAttribute(attn_kernel, cudaFuncAttributeMaxDynamicSharedMemorySize,
                         (int)smem);
    attn_kernel<<<B * NH * nblk, 256, smem>>>(pq, pk, pv, mask, pctx, S, nblk);

    gemm_kernel<1><<<grid, 256>>>(pctx, wo, bo, hidden, py, M, S);

    ln_kernel<<<M, 256>>>(py, lng, lnb, (float*)d_out);
}

// round 3
// speedup vs baseline: 2.2923x; 2.2923x over previous
#include <cuda_runtime.h>
#include <stdint.h>
#include <math.h>

#define HID 1024
#define NH 16
#define HD 64
#define BLK 64
#define MAXM 16384
#define NEGV -1000000000.0f

// Scratch (device globals: no allocations allowed)
__device__ float g_q[MAXM * HID];
__device__ float g_k[MAXM * HID];
__device__ float g_v[MAXM * HID];
__device__ float g_ctx[MAXM * HID];
__device__ float g_y[MAXM * HID];

// ---------------------------------------------------------------------------
// helpers
// ---------------------------------------------------------------------------
__device__ __forceinline__ uint32_t f2tf(float f) {
    uint32_t r;
    asm("cvt.rna.tf32.f32 %0, %1;" : "=r"(r) : "f"(f));
    return r;
}

__device__ __forceinline__ void mma8(float* c, const uint32_t* a, const uint32_t* b) {
    asm volatile(
        "mma.sync.aligned.m16n8k8.row.col.f32.tf32.tf32.f32 "
        "{%0,%1,%2,%3}, {%4,%5,%6,%7}, {%8,%9}, {%0,%1,%2,%3};"
        : "+f"(c[0]), "+f"(c[1]), "+f"(c[2]), "+f"(c[3])
        : "r"(a[0]), "r"(a[1]), "r"(a[2]), "r"(a[3]), "r"(b[0]), "r"(b[1]));
}

__device__ __forceinline__ void cpasync16(uint32_t dst, const void* src) {
    asm volatile("cp.async.cg.shared.global [%0], [%1], 16;" :: "r"(dst), "l"(src));
}
__device__ __forceinline__ void cpcommit() { asm volatile("cp.async.commit_group;"); }
__device__ __forceinline__ void cpwait0()  { asm volatile("cp.async.wait_group 0;"); }

// ---------------------------------------------------------------------------
// tf32 tensor-core GEMM: out[m,n] = sum_k X[m,k]*W[n,k] + bias[n]
// MODE 0: write transposed [(b*NH+h)*S + t]*64 + d   (QKV)
// MODE 1: write row-major + residual                 (O-proj)
// 128x128 tile, 256 threads (4x2 warps), k-chunk 32, cp.async double buffer.
// smem stride 36 (== 4 mod 32): quad-pattern fragment loads are conflict-free.
// ---------------------------------------------------------------------------
#define KC 32
#define ST 36
#define GEMM_SMEM (4 * 128 * ST * 4)   // bytes

template <int MODE>
__global__ void __launch_bounds__(256, 2)
gemm_tc(const float* __restrict__ X, const float* __restrict__ W,
        const float* __restrict__ bias, const float* __restrict__ resid,
        float* __restrict__ out, int M, int S)
{
    extern __shared__ float smem[];
    float* bufA[2] = { smem,                smem + 2 * 128 * ST };
    float* bufB[2] = { smem + 128 * ST,     smem + 3 * 128 * ST };

    const int tid  = threadIdx.x;
    const int lane = tid & 31;
    const int wid  = tid >> 5;
    const int gid  = lane >> 2;
    const int tig  = lane & 3;
    const int wm   = wid & 3;     // 4 warps along M (32 rows each)
    const int wn   = wid >> 2;    // 2 warps along N (64 cols each)
    const int mBase = blockIdx.y * 128;
    const int nBase = blockIdx.x * 128;

    const uint32_t sbase = (uint32_t)__cvta_generic_to_shared(smem);
    const int lrow = tid >> 3;            // 0..31
    const int lkq  = (tid & 7) << 2;      // 0,4,..,28

    float acc[2][8][4];
#pragma unroll
    for (int mt = 0; mt < 2; ++mt)
#pragma unroll
        for (int nt = 0; nt < 8; ++nt)
#pragma unroll
            for (int j = 0; j < 4; ++j) acc[mt][nt][j] = 0.f;

    // first chunk load
    {
        const float* xa = X + (size_t)mBase * HID;
        const float* wb = W + (size_t)nBase * HID;
        uint32_t dA = sbase;
        uint32_t dB = sbase + (uint32_t)(128 * ST * 4);
#pragma unroll
        for (int i = 0; i < 4; ++i) {
            int r = lrow + i * 32;
            cpasync16(dA + (uint32_t)((r * ST + lkq) * 4), xa + (size_t)r * HID + lkq);
            cpasync16(dB + (uint32_t)((r * ST + lkq) * 4), wb + (size_t)r * HID + lkq);
        }
        cpcommit();
    }

    const int NCH = HID / KC;   // 32
    for (int c = 0; c < NCH; ++c) {
        cpwait0();
        __syncthreads();
        if (c + 1 < NCH) {
            int kc = (c + 1) * KC;
            int s = (c + 1) & 1;
            const float* xa = X + (size_t)mBase * HID + kc;
            const float* wb = W + (size_t)nBase * HID + kc;
            uint32_t dA = sbase + (uint32_t)((s ? 2 * 128 * ST : 0) * 4);
            uint32_t dB = sbase + (uint32_t)(((s ? 3 : 1) * 128 * ST) * 4);
#pragma unroll
            for (int i = 0; i < 4; ++i) {
                int r = lrow + i * 32;
                cpasync16(dA + (uint32_t)((r * ST + lkq) * 4), xa + (size_t)r * HID + lkq);
                cpasync16(dB + (uint32_t)((r * ST + lkq) * 4), wb + (size_t)r * HID + lkq);
            }
            cpcommit();
        }

        const float* pa = bufA[c & 1];
        const float* pb = bufB[c & 1];
#pragma unroll
        for (int kk = 0; kk < KC; kk += 8) {
            uint32_t af[2][4], bf[8][2];
#pragma unroll
            for (int mt = 0; mt < 2; ++mt) {
                int r0 = wm * 32 + mt * 16 + gid;
                af[mt][0] = f2tf(pa[r0 * ST + kk + tig]);
                af[mt][1] = f2tf(pa[(r0 + 8) * ST + kk + tig]);
                af[mt][2] = f2tf(pa[r0 * ST + kk + tig + 4]);
                af[mt][3] = f2tf(pa[(r0 + 8) * ST + kk + tig + 4]);
            }
#pragma unroll
            for (int nt = 0; nt < 8; ++nt) {
                int c0 = wn * 64 + nt * 8 + gid;
                bf[nt][0] = f2tf(pb[c0 * ST + kk + tig]);
                bf[nt][1] = f2tf(pb[c0 * ST + kk + tig + 4]);
            }
#pragma unroll
            for (int mt = 0; mt < 2; ++mt)
#pragma unroll
                for (int nt = 0; nt < 8; ++nt)
                    mma8(acc[mt][nt], af[mt], bf[nt]);
        }
        __syncthreads();
    }

    // epilogue
#pragma unroll
    for (int mt = 0; mt < 2; ++mt)
#pragma unroll
        for (int i = 0; i < 2; ++i) {
            int m = mBase + wm * 32 + mt * 16 + gid + i * 8;
#pragma unroll
            for (int nt = 0; nt < 8; ++nt) {
                int n = nBase + wn * 64 + nt * 8 + 2 * tig;
                float v0 = acc[mt][nt][i * 2 + 0] + bias[n];
                float v1 = acc[mt][nt][i * 2 + 1] + bias[n + 1];
                if (MODE == 0) {
                    int bb = m / S;
                    int t = m - bb * S;
                    int h = n >> 6;
                    int d = n & 63;
                    float2* o = (float2*)(out + ((size_t)(bb * NH + h) * S + t) * HD + d);
                    *o = make_float2(v0, v1);
                } else {
                    size_t off = (size_t)m * HID + n;
                    float2 rr = *(const float2*)(resid + off);
                    *(float2*)(out + off) = make_float2(v0 + rr.x, v1 + rr.y);
                }
            }
        }
}

// ---------------------------------------------------------------------------
// Block-sparse attention with tf32 mma. One CTA per (b,h,qblock), 256 thr.
// smem: qs[64*68] kv[64*68] sc[64*260] am[256] sinv[64]
// Warp layout: wm = wid>>2 (2 warps x 32 rows), wn = wid&3 (4 warps x 16 cols)
// ---------------------------------------------------------------------------
#define ATTN_SMEM ((64*68 + 64*68 + 64*260 + 256 + 64) * 4)

__global__ void __launch_bounds__(256)
attn_tc(const float* __restrict__ gq, const float* __restrict__ gk,
        const float* __restrict__ gv, const float* __restrict__ mask,
        float* __restrict__ gctx, int S, int nblk)
{
    extern __shared__ float sm[];
    float* qs   = sm;               // 64*68
    float* kv   = qs + 64 * 68;     // 64*68
    float* sc   = kv + 64 * 68;     // 64*260
    float* am   = sc + 64 * 260;    // 256
    float* sinv = am + 256;         // 64

    const int tid  = threadIdx.x;
    const int lane = tid & 31;
    const int wid  = tid >> 5;
    const int gid  = lane >> 2;
    const int tig  = lane & 3;
    const int wm   = wid >> 2;    // 0/1 : rows 32*wm
    const int wn   = wid & 3;     // 0..3: cols 16*wn

    const int qb = blockIdx.x % nblk;
    const int bh = blockIdx.x / nblk;
    const int b  = bh >> 4;
    const int h  = bh & 15;

    // BigBird layout: [0, qb-1, qb, qb+1], dedup + range-check
    int cnd[4] = {0, qb - 1, qb, qb + 1};
    int kbi[4], vld[4];
#pragma unroll
    for (int c = 0; c < 4; ++c) {
        int cc = cnd[c];
        int ok = (cc >= 0 && cc < nblk);
#pragma unroll
        for (int j = 0; j < 4; ++j)
            if (j < c && vld[j] && cnd[j] == cc) ok = 0;
        vld[c] = ok;
        kbi[c] = min(max(cc, 0), nblk - 1);
    }

    // Q tile (pre-scaled by 1/sqrt(64)) + additive mask row
    {
        const float* qptr = gq + ((size_t)bh * S + (size_t)qb * BLK) * HD;
        for (int i = tid; i < BLK * HD; i += 256)
            qs[(i >> 6) * 68 + (i & 63)] = qptr[i] * 0.125f;
        int m = tid >> 6, c = tid & 63;
        am[tid] = vld[m] ? mask[(size_t)b * S + (size_t)kbi[m] * BLK + c] : NEGV;
    }

    // ---- scores ----
    for (int m = 0; m < 4; ++m) {
        __syncthreads();
        if (vld[m]) {
            const float* kptr = gk + ((size_t)bh * S + (size_t)kbi[m] * BLK) * HD;
            for (int i = tid; i < BLK * HD; i += 256)
                kv[(i >> 6) * 68 + (i & 63)] = kptr[i];
        }
        __syncthreads();

        if (vld[m]) {
            float acc[2][2][4] = {};
#pragma unroll
            for (int kk = 0; kk < HD; kk += 8) {
                uint32_t af[2][4], bf[2][2];
#pragma unroll
                for (int mt = 0; mt < 2; ++mt) {
                    int r0 = wm * 32 + mt * 16 + gid;
                    af[mt][0] = f2tf(qs[r0 * 68 + kk + tig]);
                    af[mt][1] = f2tf(qs[(r0 + 8) * 68 + kk + tig]);
                    af[mt][2] = f2tf(qs[r0 * 68 + kk + tig + 4]);
                    af[mt][3] = f2tf(qs[(r0 + 8) * 68 + kk + tig + 4]);
                }
#pragma unroll
                for (int nt = 0; nt < 2; ++nt) {
                    int c0 = wn * 16 + nt * 8 + gid;
                    bf[nt][0] = f2tf(kv[c0 * 68 + kk + tig]);
                    bf[nt][1] = f2tf(kv[c0 * 68 + kk + tig + 4]);
                }
#pragma unroll
                for (int mt = 0; mt < 2; ++mt)
#pragma unroll
                    for (int nt = 0; nt < 2; ++nt)
                        mma8(acc[mt][nt], af[mt], bf[nt]);
            }
#pragma unroll
            for (int mt = 0; mt < 2; ++mt)
#pragma unroll
                for (int i = 0; i < 2; ++i) {
                    int r = wm * 32 + mt * 16 + gid + i * 8;
#pragma unroll
                    for (int nt = 0; nt < 2; ++nt) {
                        int c = wn * 16 + nt * 8 + 2 * tig;
                        float2 v;
                        v.x = acc[mt][nt][i * 2 + 0] + am[m * 64 + c];
                        v.y = acc[mt][nt][i * 2 + 1] + am[m * 64 + c + 1];
                        *(float2*)(sc + r * 260 + m * 64 + c) = v;
                    }
                }
        } else {
            for (int i = tid; i < BLK * BLK; i += 256)
                sc[(i >> 6) * 260 + m * 64 + (i & 63)] = NEGV;
        }
    }
    __syncthreads();

    // ---- softmax over 256 per row (4 lanes per row) ----
    {
        const int r = tid >> 2, cs = tid & 3;
        float mx = -3.0e38f;
#pragma unroll
        for (int m = 0; m < 4; ++m)
#pragma unroll
            for (int i = 0; i < 16; ++i)
                mx = fmaxf(mx, sc[r * 260 + m * 64 + cs + 4 * i]);
        mx = fmaxf(mx, __shfl_xor_sync(0xffffffffu, mx, 1));
        mx = fmaxf(mx, __shfl_xor_sync(0xffffffffu, mx, 2));

        float sum = 0.f;
#pragma unroll
        for (int m = 0; m < 4; ++m)
#pragma unroll
            for (int i = 0; i < 16; ++i) {
                int o = r * 260 + m * 64 + cs + 4 * i;
                float e = expf(sc[o] - mx);
                sc[o] = e;
                sum += e;
            }
        sum += __shfl_xor_sync(0xffffffffu, sum, 1);
        sum += __shfl_xor_sync(0xffffffffu, sum, 2);
        if (cs == 0) sinv[r] = 1.f / sum;
    }

    // ---- ctx = P @ V ----
    float ctx[2][2][4] = {};
    for (int m = 0; m < 4; ++m) {
        __syncthreads();
        if (vld[m]) {
            const float* vptr = gv + ((size_t)bh * S + (size_t)kbi[m] * BLK) * HD;
            for (int i = tid; i < BLK * HD; i += 256)
                kv[(i >> 6) * 68 + (i & 63)] = vptr[i];
        }
        __syncthreads();

        if (vld[m]) {
#pragma unroll
            for (int kk = 0; kk < BLK; kk += 8) {
                uint32_t af[2][4], bf[2][2];
#pragma unroll
                for (int mt = 0; mt < 2; ++mt) {
                    int r0 = wm * 32 + mt * 16 + gid;
                    af[mt][0] = f2tf(sc[r0 * 260 + m * 64 + kk + tig]);
                    af[mt][1] = f2tf(sc[(r0 + 8) * 260 + m * 64 + kk + tig]);
                    af[mt][2] = f2tf(sc[r0 * 260 + m * 64 + kk + tig + 4]);
                    af[mt][3] = f2tf(sc[(r0 + 8) * 260 + m * 64 + kk + tig + 4]);
                }
#pragma unroll
                for (int nt = 0; nt < 2; ++nt) {
                    int c0 = wn * 16 + nt * 8;
                    bf[nt][0] = f2tf(kv[(kk + tig) * 68 + c0 + gid]);
                    bf[nt][1] = f2tf(kv[(kk + tig + 4) * 68 + c0 + gid]);
                }
#pragma unroll
                for (int mt = 0; mt < 2; ++mt)
#pragma unroll
                    for (int nt = 0; nt < 2; ++nt)
                        mma8(ctx[mt][nt], af[mt], bf[nt]);
            }
        }
    }

    // write ctx * inv, row-major layout for O-proj GEMM
#pragma unroll
    for (int mt = 0; mt < 2; ++mt)
#pragma unroll
        for (int i = 0; i < 2; ++i) {
            int r = wm * 32 + mt * 16 + gid + i * 8;
            float iv = sinv[r];
            int t = qb * BLK + r;
            float* o = gctx + ((size_t)(b * S + t)) * HID + h * HD;
#pragma unroll
            for (int nt = 0; nt < 2; ++nt) {
                int c = wn * 16 + nt * 8 + 2 * tig;
                *(float2*)(o + c) = make_float2(ctx[mt][nt][i * 2 + 0] * iv,
                                                ctx[mt][nt][i * 2 + 1] * iv);
            }
        }
}

// ---------------------------------------------------------------------------
// LayerNorm: one CTA (256 threads) per row of 1024.
// ---------------------------------------------------------------------------
__device__ __forceinline__ float blockReduceSum(float v)
{
    __shared__ float red[8];
    __syncthreads();
    const int lane = threadIdx.x & 31;
    const int wid = threadIdx.x >> 5;
#pragma unroll
    for (int o = 16; o; o >>= 1) v += __shfl_xor_sync(0xffffffffu, v, o);
    if (lane == 0) red[wid] = v;
    __syncthreads();
    float t = (lane < 8) ? red[lane] : 0.f;
    if (wid == 0) {
#pragma unroll
        for (int o = 4; o; o >>= 1) t += __shfl_xor_sync(0xffffffffu, t, o);
        if (lane == 0) red[0] = t;
    }
    __syncthreads();
    return red[0];
}

__global__ void __launch_bounds__(256)
ln_kernel(const float* __restrict__ y, const float* __restrict__ g,
          const float* __restrict__ bt, float* __restrict__ out)
{
    const int row = blockIdx.x;
    const int t = threadIdx.x;
    float4 v = ((const float4*)(y + (size_t)row * HID))[t];

    float s = v.x + v.y + v.z + v.w;
    float mu = blockReduceSum(s) * (1.0f / HID);

    float dx = v.x - mu, dy = v.y - mu, dz = v.z - mu, dw = v.w - mu;
    float sq = dx * dx + dy * dy + dz * dz + dw * dw;
    float var = blockReduceSum(sq) * (1.0f / HID);
    float invs = rsqrtf(var + 1e-12f);

    float4 gg = ((const float4*)g)[t];
    float4 bb = ((const float4*)bt)[t];
    float4 o;
    o.x = dx * invs * gg.x + bb.x;
    o.y = dy * invs * gg.y + bb.y;
    o.z = dz * invs * gg.z + bb.z;
    o.w = dw * invs * gg.w + bb.w;
    ((float4*)(out + (size_t)row * HID))[t] = o;
}

// ---------------------------------------------------------------------------
extern "C" void kernel_launch(void* const* d_in, const int* in_sizes, int n_in,
                              void* d_out, int out_size)
{
    const float* hidden = (const float*)d_in[0];
    const float* mask   = (const float*)d_in[1];
    const float* wq = (const float*)d_in[2];
    const float* bq = (const float*)d_in[3];
    const float* wk = (const float*)d_in[4];
    const float* bk = (const float*)d_in[5];
    const float* wv = (const float*)d_in[6];
    const float* bv = (const float*)d_in[7];
    const float* wo = (const float*)d_in[8];
    const float* bo = (const float*)d_in[9];
    const float* lng = (const float*)d_in[10];
    const float* lnb = (const float*)d_in[11];

    const int M = in_sizes[1];   // b * s = 16384
    const int S = 4096;
    const int B = M / S;
    const int nblk = S / BLK;

    float *pq, *pk, *pv, *pctx, *py;
    cudaGetSymbolAddress((void**)&pq, g_q);
    cudaGetSymbolAddress((void**)&pk, g_k);
    cudaGetSymbolAddress((void**)&pv, g_v);
    cudaGetSymbolAddress((void**)&pctx, g_ctx);
    cudaGetSymbolAddress((void**)&py, g_y);

    cudaFuncSetAttribute(gemm_tc<0>, cudaFuncAttributeMaxDynamicSharedMemorySize, GEMM_SMEM);
    cudaFuncSetAttribute(gemm_tc<1>, cudaFuncAttributeMaxDynamicSharedMemorySize, GEMM_SMEM);
    cudaFuncSetAttribute(attn_tc, cudaFuncAttributeMaxDynamicSharedMemorySize, ATTN_SMEM);

    dim3 grid(HID / 128, M / 128);
    gemm_tc<0><<<grid, 256, GEMM_SMEM>>>(hidden, wq, bq, nullptr, pq, M, S);
    gemm_tc<0><<<grid, 256, GEMM_SMEM>>>(hidden, wk, bk, nullptr, pk, M, S);
    gemm_tc<0><<<grid, 256, GEMM_SMEM>>>(hidden, wv, bv, nullptr, pv, M, S);

    attn_tc<<<B * NH * nblk, 256, ATTN_SMEM>>>(pq, pk, pv, mask, pctx, S, nblk);

    gemm_tc<1><<<grid, 256, GEMM_SMEM>>>(pctx, wo, bo, hidden, py, M, S);

    ln_kernel<<<M, 256>>>(py, lng, lnb, (float*)d_out);
}